// round 7
// baseline (speedup 1.0000x reference)
#include <cuda_runtime.h>
#include <cuda_bf16.h>

// B=128, N=512, K=510 diagonals (offsets 1..510). out = (loss[B], loss[B]).
#define NN      512
#define KD      510
#define PAIRS   255      // pair t <-> 509-t : total length 513 each
#define SPLIT   4        // pair-chunks per batch
#define CHUNK   64       // pairs per CTA
#define TPB     512      // 64 pair-lanes x 8 segments
#define NSEG    8
#define MAXB    256

__device__ float g_partial[MAXB * SPLIT];
__device__ int   g_count[MAXB];        // zero-init; reset by last block each replay

__global__ __launch_bounds__(TPB, 3)
void diag_stats_fused(const float* __restrict__ S, float* __restrict__ out,
                      int B, int out_size) {
    const int b   = blockIdx.x;
    const int s   = blockIdx.y;
    const int tid = threadIdx.x;
    const int pl  = tid & (CHUNK - 1);   // pair lane 0..63
    const int seg = tid >> 6;            // p-phase 0..7
    const int pid = s * CHUNK + pl;      // global pair id
    const float* __restrict__ M = S + (size_t)b * NN * NN;

    float sA = 0.f, qA = 0.f, sB = 0.f, qB = 0.f;

    if (pid < PAIRS) {
        const int lenA = 511 - pid;              // diag offset pid+1
        const int lenB = 2 + pid;                // diag offset 510-pid
        const float* pa = M + pid + 1;           // elem p at pa[p*513]
        const float* pb = M + 510 - pid;

        // A-diagonal: explicit 8-deep load batching -> 8 independent LDGs
        // in flight before any accumulate. Warp lanes = consecutive pid at
        // the same p -> one contiguous 128B region per warp-load.
        int p = seg;
        const int stepBig = 8 * NSEG;            // 64
        for (; p + 7 * NSEG < lenA; p += stepBig) {
            const float* q = pa + p * (NN + 1);
            float x0 = __ldcs(q + 0 * NSEG * (NN + 1));
            float x1 = __ldcs(q + 1 * NSEG * (NN + 1));
            float x2 = __ldcs(q + 2 * NSEG * (NN + 1));
            float x3 = __ldcs(q + 3 * NSEG * (NN + 1));
            float x4 = __ldcs(q + 4 * NSEG * (NN + 1));
            float x5 = __ldcs(q + 5 * NSEG * (NN + 1));
            float x6 = __ldcs(q + 6 * NSEG * (NN + 1));
            float x7 = __ldcs(q + 7 * NSEG * (NN + 1));
            sA += x0; qA += x0 * x0;
            sA += x1; qA += x1 * x1;
            sA += x2; qA += x2 * x2;
            sA += x3; qA += x3 * x3;
            sA += x4; qA += x4 * x4;
            sA += x5; qA += x5 * x5;
            sA += x6; qA += x6 * x6;
            sA += x7; qA += x7 * x7;
        }
        for (; p < lenA; p += NSEG) {
            float x = __ldcs(pa + p * (NN + 1));
            sA += x; qA += x * x;
        }

        // B-diagonal (short: 2..256 elems), 4-deep batching.
        p = seg;
        for (; p + 3 * NSEG < lenB; p += 4 * NSEG) {
            const float* q = pb + p * (NN + 1);
            float x0 = __ldcs(q + 0 * NSEG * (NN + 1));
            float x1 = __ldcs(q + 1 * NSEG * (NN + 1));
            float x2 = __ldcs(q + 2 * NSEG * (NN + 1));
            float x3 = __ldcs(q + 3 * NSEG * (NN + 1));
            sB += x0; qB += x0 * x0;
            sB += x1; qB += x1 * x1;
            sB += x2; qB += x2 * x2;
            sB += x3; qB += x3 * x3;
        }
        for (; p < lenB; p += NSEG) {
            float x = __ldcs(pb + p * (NN + 1));
            sB += x; qB += x * x;
        }
    }

    // Combine the 8 segment partials per pair.
    __shared__ float sh[4][NSEG][CHUNK];   // 8 KB
    sh[0][seg][pl] = sA;
    sh[1][seg][pl] = qA;
    sh[2][seg][pl] = sB;
    sh[3][seg][pl] = qB;
    __syncthreads();

    __shared__ float red[CHUNK];
    if (tid < CHUNK) {
        float contrib = 0.f;
        if (pid < PAIRS) {
            float SA = 0.f, QA = 0.f, SB = 0.f, QB = 0.f;
            #pragma unroll
            for (int g = 0; g < NSEG; ++g) {
                SA += sh[0][g][tid];
                QA += sh[1][g][tid];
                SB += sh[2][g][tid];
                QB += sh[3][g][tid];
            }
            const float lA = (float)(511 - pid);
            const float lB = (float)(2 + pid);
            float mA = SA / lA;
            float vA = fmaxf((QA - SA * mA) / (lA - 1.0f), 0.0f);
            float mB = SB / lB;
            float vB = fmaxf((QB - SB * mB) / (lB - 1.0f), 0.0f);
            contrib = sqrtf(vA) * lA * 0.2f + sqrtf(vB) * lB * 0.2f;
        }
        red[tid] = contrib;
    }
    __syncthreads();

    if (tid < 32) {
        float v = red[tid] + red[tid + 32];
        #pragma unroll
        for (int off = 16; off > 0; off >>= 1)
            v += __shfl_down_sync(0xFFFFFFFFu, v, off);

        if (tid == 0) {
            g_partial[b * SPLIT + s] = v;
            __threadfence();
            int old = atomicAdd(&g_count[b], 1);
            if (old == SPLIT - 1) {
                float acc = 0.f;
                #pragma unroll
                for (int i = 0; i < SPLIT; ++i)
                    acc += g_partial[b * SPLIT + i];
                float loss = acc / (float)KD;
                out[b] = loss;
                if (out_size >= 2 * B) out[B + b] = loss;
                g_count[b] = 0;   // reset for next graph replay
            }
        }
    }
}

extern "C" void kernel_launch(void* const* d_in, const int* in_sizes, int n_in,
                              void* d_out, int out_size) {
    const float* S = (const float*)d_in[0];
    float* out = (float*)d_out;
    const int B = in_sizes[0] / (NN * NN);
    dim3 grid(B, SPLIT);
    diag_stats_fused<<<grid, TPB>>>(S, out, B, out_size);
}

// round 8
// speedup vs baseline: 1.0877x; 1.0877x over previous
#include <cuda_runtime.h>
#include <cuda_bf16.h>

// B=128, N=512, diagonals k=0..509 (offset k+1), len(k)=511-k.
// out = (loss[B], loss[B]).
//
// Quad scheme: aligned float4 at (row p, col 4m) belongs to group j=4m-p.
// Its 4 elements lie on diagonals k_e = j+e-1 (e=0..3), constant along p+=4.
// Thread owns jA = (q-2)+4*la and jB = 507-jA; warp lanes give contiguous
// 512B LDG.128 per row. Out-of-range (j,e) combos are never read back.
#define NN   512
#define KD   510
#define TPB  512
#define RSG  3          // grid row-split CTAs per batch
#define RST  6          // total row splits (RSG * 2 in-CTA)
#define MAXB 256

__device__ float2 g_part[MAXB * RSG * 512];
__device__ int    g_count[MAXB];     // zero-init; reset by last CTA each replay

__global__ __launch_bounds__(TPB, 3)
void diag_quad(const float* __restrict__ S, float* __restrict__ out,
               int B, int out_size) {
    const int b    = blockIdx.x;
    const int rsg  = blockIdx.y;
    const int tid  = threadIdx.x;
    const int lane = tid & 31;
    const int w    = tid >> 5;       // 0..15
    const int rs   = w >> 3;         // in-CTA row split 0..1
    const int q    = w & 3;          // alignment class
    const int h    = (w >> 2) & 1;   // lane-half
    const int la   = h * 32 + lane;  // 0..63
    const int jA   = q - 2 + 4 * la;       // -2..253
    const int jB   = 509 - q - 4 * la;     // 509..254  (= 507 - jA)
    const int rst  = rsg * 2 + rs;         // 0..5

    const float* __restrict__ M = S + (size_t)b * NN * NN;

    float sA[4] = {0,0,0,0}, qA[4] = {0,0,0,0};
    float sB[4] = {0,0,0,0}, qB[4] = {0,0,0,0};

    // ---- side A: j = jA, rows p ≡ (2-q) mod 4, col base p+jA (16B aligned)
    {
        int p = ((2 - q) & 3) + 4 * rst;
        const int pend = 510 - q - 128 * h;      // exact for lane la=32h
        const float* ptr = M + (size_t)p * (NN + 1) + jA;
        #pragma unroll 2
        for (; p <= pend; p += 4 * RST, ptr += 4 * RST * (NN + 1)) {
            float4 x = __ldcs((const float4*)ptr);
            float vf = (p + jA <= 508) ? 1.0f : 0.0f;
            float y0 = x.x * vf, y1 = x.y * vf, y2 = x.z * vf, y3 = x.w * vf;
            sA[0] += y0; qA[0] = fmaf(y0, x.x, qA[0]);
            sA[1] += y1; qA[1] = fmaf(y1, x.y, qA[1]);
            sA[2] += y2; qA[2] = fmaf(y2, x.z, qA[2]);
            sA[3] += y3; qA[3] = fmaf(y3, x.w, qA[3]);
        }
    }
    // ---- side B: j = jB, rows p ≡ (q+3) mod 4, lanes descending cols (still 512B)
    {
        int p = ((q + 3) & 3) + 4 * rst;
        const int pend = 123 + q + 128 * h;      // exact for lane la=32h+31
        const float* ptr = M + (size_t)p * (NN + 1) + jB;
        #pragma unroll 2
        for (; p <= pend; p += 4 * RST, ptr += 4 * RST * (NN + 1)) {
            float4 x = __ldcs((const float4*)ptr);
            float vf = (p + jB <= 508) ? 1.0f : 0.0f;
            float y0 = x.x * vf, y1 = x.y * vf, y2 = x.z * vf, y3 = x.w * vf;
            sB[0] += y0; qB[0] = fmaf(y0, x.x, qB[0]);
            sB[1] += y1; qB[1] = fmaf(y1, x.y, qB[1]);
            sB[2] += y2; qB[2] = fmaf(y2, x.z, qB[2]);
            sB[3] += y3; qB[3] = fmaf(y3, x.w, qB[3]);
        }
    }

    // ---- deterministic (j,e) combine in smem: slot = j+2 in 0..511, one owner.
    __shared__ float psum[512][9];     // [slot][2e+stat], padded
    const int slotA = q + 4 * la;      // jA+2 : 0..255
    const int slotB = 511 - slotA;     // jB+2 : 256..511
    if (rs == 0) {
        #pragma unroll
        for (int e = 0; e < 4; ++e) {
            psum[slotA][2*e]   = sA[e];
            psum[slotA][2*e+1] = qA[e];
            psum[slotB][2*e]   = sB[e];
            psum[slotB][2*e+1] = qB[e];
        }
    }
    __syncthreads();
    if (rs == 1) {
        #pragma unroll
        for (int e = 0; e < 4; ++e) {
            psum[slotA][2*e]   += sA[e];
            psum[slotA][2*e+1] += qA[e];
            psum[slotB][2*e]   += sB[e];
            psum[slotB][2*e+1] += qB[e];
        }
    }
    __syncthreads();

    // ---- per-diag CTA partial: diag k <- (j=k+1-e, e), slot=k+3-e
    if (tid < KD) {
        float Ss = 0.f, Qs = 0.f;
        #pragma unroll
        for (int e = 0; e < 4; ++e) {
            int slot = tid + 3 - e;
            if (slot <= 511) { Ss += psum[slot][2*e]; Qs += psum[slot][2*e+1]; }
        }
        g_part[(b * RSG + rsg) * 512 + tid] = make_float2(Ss, Qs);
    }
    __threadfence();
    __syncthreads();

    __shared__ int is_last;
    if (tid == 0) {
        int old = atomicAdd(&g_count[b], 1);
        is_last = (old == RSG - 1);
        if (old == RSG - 1) g_count[b] = 0;   // reset for next graph replay
    }
    __syncthreads();

    if (is_last) {
        float contrib = 0.f;
        if (tid < KD) {
            float Ss = 0.f, Qs = 0.f;
            #pragma unroll
            for (int i = 0; i < RSG; ++i) {            // fixed order: deterministic
                float2 v = g_part[(b * RSG + i) * 512 + tid];
                Ss += v.x; Qs += v.y;
            }
            const float len = 511.0f - (float)tid;
            float mean = Ss / len;
            float var  = fmaxf((Qs - Ss * mean) / (len - 1.0f), 0.0f);
            contrib = sqrtf(var) * len * 0.2f;
        }
        __shared__ float red[TPB];
        red[tid] = contrib;
        __syncthreads();
        #pragma unroll
        for (int s = TPB / 2; s >= 32; s >>= 1) {
            if (tid < s) red[tid] += red[tid + s];
            __syncthreads();
        }
        if (tid < 32) {
            float v = red[tid];
            #pragma unroll
            for (int off = 16; off > 0; off >>= 1)
                v += __shfl_down_sync(0xFFFFFFFFu, v, off);
            if (tid == 0) {
                float loss = v / (float)KD;
                out[b] = loss;
                if (out_size >= 2 * B) out[B + b] = loss;
            }
        }
    }
}

extern "C" void kernel_launch(void* const* d_in, const int* in_sizes, int n_in,
                              void* d_out, int out_size) {
    const float* S = (const float*)d_in[0];
    float* out = (float*)d_out;
    const int B = in_sizes[0] / (NN * NN);
    dim3 grid(B, RSG);
    diag_quad<<<grid, TPB>>>(S, out, B, out_size);
}